// round 12
// baseline (speedup 1.0000x reference)
#include <cuda_runtime.h>
#include <cuda_fp16.h>
#include <math.h>
#include <stdint.h>

// ---------------------------------------------------------------------------
// GatedBlock via mma.sync fp16 implicit GEMM (single-term):
//   D = x_f16 * w_f16 ;  conv3d(72->176,k5,pad2) => D[M=128, N=176], K=72*128
//   gate fused into the GEMM epilogue, then separable gaussian stride-2.
// Round 12: conv = round-10 state (best known); lowpass = coalesced bulk load
//           + 3 separable passes fully inside smem.
// ---------------------------------------------------------------------------

#define B_      4
#define CI_     72
#define CO_     176
#define NSP_    (32*32*32)
#define NCH_    144

#define NCHUNK_ 72            // one input channel per chunk (K=128)
#define A_HALF  16384         // 128 rows x 64 fp16
#define A_TILE  (2*A_HALF)    // [khalf][128][64]
#define B_HALF  22528         // 176 rows x 64 fp16
#define B_TILE  (2*B_HALF)    // [khalf][176][64]
#define NT_     512

__device__ float  g_z[(size_t)B_ * NCH_ * NSP_];
__device__ __half g_wprep[(size_t)NCHUNK_ * CO_ * 128];   // fp16, pre-swizzled
__device__ __half g_xh[(size_t)B_ * CI_ * NSP_];          // fp16 x image

// ---- smem byte offsets (dynamic smem, conv kernel) ----
// [0, 92928) is reused by the epilogue sD[176][132]; persistent data above it.
#define SA_OFF    0                        // A: 2 x 32768 = 65536
#define SB_OFF    65536                    // B: 2 x 45056 -> 155648
#define SX_OFF    155648                   // xs: 1584 halves -> 158816
#define XS_VALS   1584
#define ST_OFF    158848                   // tapoff: 128 ints -> 159360
#define SSB_OFF   159360
#define SGB_OFF   159424
#define SMEM_TOTAL 159552

// ---- lowpass smem layout (floats) ----
#define LP_IN_OFF  0                       // sIn[7][35][36]
#define LP_T1_OFF  (7*35*36)               // sT1[7][35][16]
#define LP_T2_OFF  (LP_T1_OFF + 7*35*16)   // sT2[7][16][16]
#define LP_SMEM    ((LP_T2_OFF + 7*16*16) * 4)

// ---------------- helpers ----------------
__device__ __forceinline__ uint32_t smem_u32(const void* p){
    uint32_t a;
    asm("{ .reg .u64 t; cvta.to.shared.u64 t, %1; cvt.u32.u64 %0, t; }"
        : "=r"(a) : "l"(p));
    return a;
}
__device__ __forceinline__ uint32_t swz(uint32_t o){
    return o ^ (((o >> 7) & 7u) << 4);
}

#define CPA16(d,s) asm volatile("cp.async.cg.shared.global [%0], [%1], 16;" :: "r"(d), "l"(s))
#define CPA4(d,s)  asm volatile("cp.async.ca.shared.global [%0], [%1], 4;"  :: "r"(d), "l"(s))
#define CPC()      asm volatile("cp.async.commit_group;")
#define CPW0()     asm volatile("cp.async.wait_group 0;")

#define LDM4(r, a) \
    asm volatile("ldmatrix.sync.aligned.m8n8.x4.shared.b16 {%0,%1,%2,%3}, [%4];" \
        : "=r"((r)[0]),"=r"((r)[1]),"=r"((r)[2]),"=r"((r)[3]) : "r"(a))

#define MMAF16(d, a, b0v, b1v) \
    asm volatile("mma.sync.aligned.m16n8k16.row.col.f32.f16.f16.f32 " \
        "{%0,%1,%2,%3}, {%4,%5,%6,%7}, {%8,%9}, {%0,%1,%2,%3};" \
        : "+f"((d)[0]),"+f"((d)[1]),"+f"((d)[2]),"+f"((d)[3]) \
        : "r"((a)[0]),"r"((a)[1]),"r"((a)[2]),"r"((a)[3]), "r"(b0v), "r"(b1v))

// ---------------------------------------------------------------------------
// Weight prep: chunk = ci; tile = [khalf][176][64] fp16, swizzle pre-applied.
// ---------------------------------------------------------------------------
__global__ void prep_kernel(const float* __restrict__ W)
{
    int e = blockIdx.x * 256 + threadIdx.x;   // 72*176*128 = 1,622,016 exact
    int col   = e & 127;
    int row   = (e >> 7) % CO_;
    int chunk = e / (CO_ * 128);
    float v = (col < 125) ? W[((size_t)row * CI_ + chunk) * 125 + col] : 0.f;
    int khalf = col >> 6, c6 = col & 63;
    uint32_t off = (uint32_t)(row * 128 + c6 * 2);
    uint32_t sw  = off ^ ((uint32_t)(row & 7) << 4);
    g_wprep[(size_t)chunk * (CO_ * 128) + (size_t)khalf * (CO_ * 64) + (sw >> 1)]
        = __float2half_rn(v);
}

__global__ void prep_x_kernel(const float* __restrict__ x)
{
    size_t i = (size_t)blockIdx.x * 256 + threadIdx.x;   // 9,437,184 exact
    g_xh[i] = __float2half_rn(x[i]);
}

// ---------------------------------------------------------------------------
// Main kernel: implicit GEMM + fused gate epilogue.  (round-10 state)
// grid (8 y-tiles, 32 z, 4 b), 512 threads. warps 4M x 4N (N=48/48/48/32).
// ---------------------------------------------------------------------------
__global__ __launch_bounds__(NT_, 1)
void conv_mma_kernel(const float* __restrict__ sbg, const float* __restrict__ gbg)
{
    extern __shared__ unsigned char smem[];
    const uint32_t smb = smem_u32(smem);

    const int tid = threadIdx.x;
    const int wid = tid >> 5;
    const int lid = tid & 31;
    const int b  = blockIdx.z;
    const int z0 = blockIdx.y;
    const int y0 = blockIdx.x * 4;

    // builder role: 16 warps = 4 y-groups x 4 k-quarters (32 k each)
    const int byy = wid & 3, bkq = wid >> 2;
    // mma role: 4 M-groups x 4 N-groups
    const int mw = wid & 3, nw = wid >> 2;
    const int m0 = mw * 32;
    const int n0 = nw * 48;                 // nw=3 -> 144
    const int NG = (nw == 3) ? 4 : 6;       // n8 groups in this warp

    __half* xs    = (__half*)(smem + SX_OFF);
    int*   tapoff = (int*)(smem + ST_OFF);
    float* sS     = (float*)(smem + SSB_OFF);
    float* sG     = (float*)(smem + SGB_OFF);

    for (int i = tid; i < XS_VALS; i += NT_) xs[i] = __ushort_as_half(0);
    if (tid < 128) {
        int tap = tid;
        int kd = tap / 25, r = tap % 25;
        int kh = r / 5, kw = r % 5;
        tapoff[tid] = (tap < 125) ? (kd * 8 + kh) * 36 + kw : 1440;
    }
    if (tid < 16) sS[tid] = sbg[tid];
    if (tid < 32) sG[tid] = gbg[tid];
    __syncthreads();

    const __half* xb = g_xh + (size_t)b * CI_ * NSP_;

    auto stage_x = [&](int ci) {
        const __half* xc = xb + (size_t)ci * NSP_;
        for (int it = tid; it < 640; it += NT_) {
            int ck = it & 15;
            int row = it >> 4;           // zi*8 + yi
            int yi = row & 7, zi = row >> 3;
            int gy = y0 + yi - 2, gz = z0 + zi - 2;
            if ((unsigned)gy < 32u && (unsigned)gz < 32u)
                CPA4(smb + SX_OFF + (uint32_t)(row * 36 + 2 + ck * 2) * 2,
                     xc + ((gz * 32 + gy) * 32 + ck * 2));
        }
    };
    auto stage_B = [&](int n, int nb) {
        const char* src = (const char*)g_wprep + (size_t)n * B_TILE;
        uint32_t dst = smb + SB_OFF + nb * B_TILE;
        for (int i = tid; i < B_TILE / 16; i += NT_)
            CPA16(dst + i * 16, src + i * 16);
    };
    auto build_A = [&](int nb) {
        char* Abase = (char*)smem + SA_OFF + nb * A_TILE;
        const int lin = byy * 36 + lid;
        const int m   = byy * 32 + lid;
        const uint32_t mx = (uint32_t)(m & 7) << 4;
#pragma unroll
        for (int j = 0; j < 16; ++j) {
            int k0 = bkq * 32 + 2 * j;
            uint32_t t0 = *(const unsigned short*)((const char*)xs +
                              (uint32_t)(tapoff[k0]     + lin) * 2);
            uint32_t t1 = *(const unsigned short*)((const char*)xs +
                              (uint32_t)(tapoff[k0 + 1] + lin) * 2);
            uint32_t hp = t0 | (t1 << 16);
            int khalf = k0 >> 6, c6 = k0 & 63;
            *(uint32_t*)(Abase + khalf * A_HALF +
                         (((uint32_t)(m * 128 + c6 * 2)) ^ mx)) = hp;
        }
    };

    // lane-invariant ldmatrix offsets
    const uint32_t aLane  = (uint32_t)((lid & 15) * 128 + ((lid & 16) ? 16 : 0));
    const uint32_t bLane4 = (uint32_t)((((lid & 7) + ((lid & 16) ? 8 : 0)) * 128) +
                                       ((lid & 8) ? 16 : 0));

    float acc[2][6][4];
#pragma unroll
    for (int mi = 0; mi < 2; ++mi)
#pragma unroll
        for (int ni = 0; ni < 6; ++ni)
#pragma unroll
            for (int r = 0; r < 4; ++r) acc[mi][ni][r] = 0.f;

    // ---- prologue ----
    stage_B(0, 0);
    stage_x(0);
    CPC(); CPW0();
    __syncthreads();
    build_A(0);
    __syncthreads();

    for (int c = 0; c < NCHUNK_; ++c) {
        const int bsel = c & 1;
        if (c + 1 < NCHUNK_) {
            stage_B(c + 1, bsel ^ 1);
            stage_x(c + 1);
            CPC();
        }

        const uint32_t AB = smb + SA_OFF + bsel * A_TILE;
        const uint32_t BB = smb + SB_OFF + bsel * B_TILE;

#pragma unroll
        for (int ks = 0; ks < 8; ++ks) {
            const uint32_t Ah = AB + (ks >> 2) * A_HALF;
            const uint32_t Bh = BB + (ks >> 2) * B_HALF;
            const uint32_t kso = (uint32_t)(ks & 3) * 32;
            uint32_t a0[4], a1[4];
            LDM4(a0, Ah + swz((uint32_t)(m0       * 128) + kso + aLane));
            LDM4(a1, Ah + swz((uint32_t)((m0+16)  * 128) + kso + aLane));
#pragma unroll
            for (int g = 0; g < 3; ++g) {
                if (g * 2 >= NG) break;
                uint32_t bh[4];
                LDM4(bh, Bh + swz((uint32_t)((n0 + g * 16) * 128) + kso + bLane4));
                MMAF16(acc[0][g * 2],     a0, bh[0], bh[1]);
                MMAF16(acc[1][g * 2],     a1, bh[0], bh[1]);
                MMAF16(acc[0][g * 2 + 1], a0, bh[2], bh[3]);
                MMAF16(acc[1][g * 2 + 1], a1, bh[2], bh[3]);
            }
        }

        if (c + 1 < NCHUNK_) {
            CPW0();
            __syncthreads();
            build_A(bsel ^ 1);
        }
        __syncthreads();
    }

    // ---- epilogue: accums -> smem, sigmoid gates, gated write to g_z ----
    float* sD = (float*)smem;   // [176][132] floats = 92928B, reuses tile smem
#pragma unroll
    for (int mi = 0; mi < 2; ++mi)
#pragma unroll
        for (int ni = 0; ni < 6; ++ni) {
            if (ni >= NG) break;
#pragma unroll
            for (int r = 0; r < 4; ++r) {
                int m  = m0 + mi * 16 + (lid >> 2) + ((r & 2) ? 8 : 0);
                int cc = n0 + ni * 8 + (lid & 3) * 2 + (r & 1);
                sD[cc * 132 + m] = acc[mi][ni][r];
            }
        }
    __syncthreads();

    for (int i = tid; i < 32 * 128; i += NT_) {
        int gi = i >> 7, mm = i & 127;
        int ad = (144 + gi) * 132 + mm;
        sD[ad] = 1.f / (1.f + expf(-(sD[ad] + sG[gi])));
    }
    __syncthreads();

    float* zb = g_z + (size_t)b * NCH_ * NSP_ + (size_t)z0 * 1024 + y0 * 32;
    for (int i = tid; i < 144 * 128; i += NT_) {
        int cc = i >> 7, mm = i & 127;
        float v = sD[cc * 132 + mm];
        float o;
        if (cc < 16) o = fmaxf(v + sS[cc], 0.f);
        else {
            int gi = (cc < 64) ? (cc - 16) / 3 : 16 + (cc - 64) / 5;
            o = v * sD[(144 + gi) * 132 + mm];
        }
        zb[(size_t)cc * NSP_ + mm] = o;
    }
}

// ---------------------------------------------------------------------------
// Separable depthwise gaussian, stride2, pad2 -> (16,16,16). grid (8,144,4).
// Coalesced bulk load into sIn[7][35][36] (high MLP), then three in-smem
// passes: x -> sT1[7][35][16], y -> sT2[7][16][16], z -> out (2 planes).
// ---------------------------------------------------------------------------
__global__ __launch_bounds__(256)
void lowpass_kernel(float* __restrict__ out)
{
    extern __shared__ float lps[];
    float* sIn = lps + LP_IN_OFF;   // [7][35][36], xi 0..34 used
    float* sT1 = lps + LP_T1_OFF;   // [7][35][16]
    float* sT2 = lps + LP_T2_OFF;   // [7][16][16]

    const int zt = blockIdx.x;
    const int c  = blockIdx.y;
    const int b  = blockIdx.z;
    const int tid = threadIdx.x;

    float g1[5];
    {
        double g[5], s = 0.0;
#pragma unroll
        for (int r = 0; r < 5; ++r) {
            double d = (double)(r - 2);
            g[r] = exp(-d * d / 1.5);   // 2*sigma^2 = 1.5
            s += g[r];
        }
#pragma unroll
        for (int r = 0; r < 5; ++r) g1[r] = (float)(g[r] / s);
    }

    const int zo0 = 2 * zt;
    const int zi0 = 2 * zo0 - 2;
    const float* zc = g_z + (size_t)(b * NCH_ + c) * NSP_;

    // bulk load, coalesced, zero-padded halo
    for (int i = tid; i < 7 * 35 * 35; i += 256) {
        int xi = i % 35;
        int t  = i / 35;
        int yi = t % 35;
        int zi = t / 35;
        int gx = xi - 2, gy = yi - 2, gz = zi0 + zi;
        float v = 0.f;
        if ((unsigned)gx < 32u && (unsigned)gy < 32u && (unsigned)gz < 32u)
            v = zc[(gz * 32 + gy) * 32 + gx];
        sIn[(zi * 35 + yi) * 36 + xi] = v;
    }
    __syncthreads();

    // pass 1: x filter (stride 2): sT1[zi][yi][xo]
    for (int i = tid; i < 7 * 35 * 16; i += 256) {
        int xo = i & 15;
        int t  = i >> 4;
        int yi = t % 35;
        int zi = t / 35;
        const float* rowp = &sIn[(zi * 35 + yi) * 36 + 2 * xo];
        float s = g1[0] * rowp[0] + g1[1] * rowp[1] + g1[2] * rowp[2]
                + g1[3] * rowp[3] + g1[4] * rowp[4];
        sT1[i] = s;
    }
    __syncthreads();

    // pass 2: y filter (stride 2): sT2[zi][yo][xo]
    for (int i = tid; i < 7 * 16 * 16; i += 256) {
        int xo = i & 15;
        int t  = i >> 4;
        int yo = t & 15;
        int zi = t >> 4;
        const float* colp = &sT1[(zi * 35 + 2 * yo) * 16 + xo];
        float s = g1[0] * colp[0]  + g1[1] * colp[16] + g1[2] * colp[32]
                + g1[3] * colp[48] + g1[4] * colp[64];
        sT2[i] = s;
    }
    __syncthreads();

    // pass 3: z filter (stride 2), 2 output planes
    const int xo = tid & 15;
    const int yo = tid >> 4;
#pragma unroll
    for (int dz = 0; dz < 2; ++dz) {
        const float* zp = &sT2[((2 * dz) * 16 + yo) * 16 + xo];
        float s = g1[0] * zp[0]     + g1[1] * zp[256]  + g1[2] * zp[512]
                + g1[3] * zp[768]   + g1[4] * zp[1024];
        out[((size_t)(b * NCH_ + c) * 16 + (zo0 + dz)) * 256 + yo * 16 + xo] = s;
    }
}

// ---------------------------------------------------------------------------
extern "C" void kernel_launch(void* const* d_in, const int* in_sizes, int n_in,
                              void* d_out, int out_size)
{
    const float* x  = (const float*)d_in[0];   // (4,72,32,32,32)
    const float* W  = (const float*)d_in[1];   // (176,72,5,5,5)
    const float* sb = (const float*)d_in[2];   // (16,)
    const float* gb = (const float*)d_in[3];   // (32,)
    float* out = (float*)d_out;                // (4,144,16,16,16)

    cudaFuncSetAttribute(conv_mma_kernel,
                         cudaFuncAttributeMaxDynamicSharedMemorySize, SMEM_TOTAL);
    cudaFuncSetAttribute(lowpass_kernel,
                         cudaFuncAttributeMaxDynamicSharedMemorySize, LP_SMEM);

    prep_kernel<<<6336, 256>>>(W);
    prep_x_kernel<<<36864, 256>>>(x);
    conv_mma_kernel<<<dim3(8, 32, B_), NT_, SMEM_TOTAL>>>(sb, gb);
    lowpass_kernel<<<dim3(8, NCH_, B_), 256, LP_SMEM>>>(out);
}

// round 13
// speedup vs baseline: 1.0742x; 1.0742x over previous
#include <cuda_runtime.h>
#include <cuda_fp16.h>
#include <math.h>
#include <stdint.h>

// ---------------------------------------------------------------------------
// GatedBlock via mma.sync fp16 implicit GEMM (single-term):
//   D = x_f16 * w_f16 ;  conv3d(72->176,k5,pad2) => D[M=128, N=176], K=72*128
//   gate fused into the GEMM epilogue, then depthwise gaussian stride-2.
// Round 13: conv = round-10 state. Lowpass: 4 z-planes/block, single barrier,
//   div-free incremental load indexing, kd-weights in registers.
// ---------------------------------------------------------------------------

#define B_      4
#define CI_     72
#define CO_     176
#define NSP_    (32*32*32)
#define NCH_    144

#define NCHUNK_ 72            // one input channel per chunk (K=128)
#define A_HALF  16384         // 128 rows x 64 fp16
#define A_TILE  (2*A_HALF)    // [khalf][128][64]
#define B_HALF  22528         // 176 rows x 64 fp16
#define B_TILE  (2*B_HALF)    // [khalf][176][64]
#define NT_     512

__device__ float  g_z[(size_t)B_ * NCH_ * NSP_];
__device__ __half g_wprep[(size_t)NCHUNK_ * CO_ * 128];   // fp16, pre-swizzled
__device__ __half g_xh[(size_t)B_ * CI_ * NSP_];          // fp16 x image

// ---- smem byte offsets (dynamic smem, conv kernel) ----
// [0, 92928) is reused by the epilogue sD[176][132]; persistent data above it.
#define SA_OFF    0                        // A: 2 x 32768 = 65536
#define SB_OFF    65536                    // B: 2 x 45056 -> 155648
#define SX_OFF    155648                   // xs: 1584 halves -> 158816
#define XS_VALS   1584
#define ST_OFF    158848                   // tapoff: 128 ints -> 159360
#define SSB_OFF   159360
#define SGB_OFF   159424
#define SMEM_TOTAL 159552

// ---- lowpass: dynamic smem sZ[11][35][36] floats ----
#define LP_SMEM   (11*35*36*4)             // 55440 B

// ---------------- helpers ----------------
__device__ __forceinline__ uint32_t smem_u32(const void* p){
    uint32_t a;
    asm("{ .reg .u64 t; cvta.to.shared.u64 t, %1; cvt.u32.u64 %0, t; }"
        : "=r"(a) : "l"(p));
    return a;
}
__device__ __forceinline__ uint32_t swz(uint32_t o){
    return o ^ (((o >> 7) & 7u) << 4);
}

#define CPA16(d,s) asm volatile("cp.async.cg.shared.global [%0], [%1], 16;" :: "r"(d), "l"(s))
#define CPA4(d,s)  asm volatile("cp.async.ca.shared.global [%0], [%1], 4;"  :: "r"(d), "l"(s))
#define CPC()      asm volatile("cp.async.commit_group;")
#define CPW0()     asm volatile("cp.async.wait_group 0;")

#define LDM4(r, a) \
    asm volatile("ldmatrix.sync.aligned.m8n8.x4.shared.b16 {%0,%1,%2,%3}, [%4];" \
        : "=r"((r)[0]),"=r"((r)[1]),"=r"((r)[2]),"=r"((r)[3]) : "r"(a))

#define MMAF16(d, a, b0v, b1v) \
    asm volatile("mma.sync.aligned.m16n8k16.row.col.f32.f16.f16.f32 " \
        "{%0,%1,%2,%3}, {%4,%5,%6,%7}, {%8,%9}, {%0,%1,%2,%3};" \
        : "+f"((d)[0]),"+f"((d)[1]),"+f"((d)[2]),"+f"((d)[3]) \
        : "r"((a)[0]),"r"((a)[1]),"r"((a)[2]),"r"((a)[3]), "r"(b0v), "r"(b1v))

// ---------------------------------------------------------------------------
// Weight prep: chunk = ci; tile = [khalf][176][64] fp16, swizzle pre-applied.
// ---------------------------------------------------------------------------
__global__ void prep_kernel(const float* __restrict__ W)
{
    int e = blockIdx.x * 256 + threadIdx.x;   // 72*176*128 = 1,622,016 exact
    int col   = e & 127;
    int row   = (e >> 7) % CO_;
    int chunk = e / (CO_ * 128);
    float v = (col < 125) ? W[((size_t)row * CI_ + chunk) * 125 + col] : 0.f;
    int khalf = col >> 6, c6 = col & 63;
    uint32_t off = (uint32_t)(row * 128 + c6 * 2);
    uint32_t sw  = off ^ ((uint32_t)(row & 7) << 4);
    g_wprep[(size_t)chunk * (CO_ * 128) + (size_t)khalf * (CO_ * 64) + (sw >> 1)]
        = __float2half_rn(v);
}

__global__ void prep_x_kernel(const float* __restrict__ x)
{
    size_t i = (size_t)blockIdx.x * 256 + threadIdx.x;   // 9,437,184 exact
    g_xh[i] = __float2half_rn(x[i]);
}

// ---------------------------------------------------------------------------
// Main kernel: implicit GEMM + fused gate epilogue.  (round-10 state)
// grid (8 y-tiles, 32 z, 4 b), 512 threads. warps 4M x 4N (N=48/48/48/32).
// ---------------------------------------------------------------------------
__global__ __launch_bounds__(NT_, 1)
void conv_mma_kernel(const float* __restrict__ sbg, const float* __restrict__ gbg)
{
    extern __shared__ unsigned char smem[];
    const uint32_t smb = smem_u32(smem);

    const int tid = threadIdx.x;
    const int wid = tid >> 5;
    const int lid = tid & 31;
    const int b  = blockIdx.z;
    const int z0 = blockIdx.y;
    const int y0 = blockIdx.x * 4;

    // builder role: 16 warps = 4 y-groups x 4 k-quarters (32 k each)
    const int byy = wid & 3, bkq = wid >> 2;
    // mma role: 4 M-groups x 4 N-groups
    const int mw = wid & 3, nw = wid >> 2;
    const int m0 = mw * 32;
    const int n0 = nw * 48;                 // nw=3 -> 144
    const int NG = (nw == 3) ? 4 : 6;       // n8 groups in this warp

    __half* xs    = (__half*)(smem + SX_OFF);
    int*   tapoff = (int*)(smem + ST_OFF);
    float* sS     = (float*)(smem + SSB_OFF);
    float* sG     = (float*)(smem + SGB_OFF);

    for (int i = tid; i < XS_VALS; i += NT_) xs[i] = __ushort_as_half(0);
    if (tid < 128) {
        int tap = tid;
        int kd = tap / 25, r = tap % 25;
        int kh = r / 5, kw = r % 5;
        tapoff[tid] = (tap < 125) ? (kd * 8 + kh) * 36 + kw : 1440;
    }
    if (tid < 16) sS[tid] = sbg[tid];
    if (tid < 32) sG[tid] = gbg[tid];
    __syncthreads();

    const __half* xb = g_xh + (size_t)b * CI_ * NSP_;

    auto stage_x = [&](int ci) {
        const __half* xc = xb + (size_t)ci * NSP_;
        for (int it = tid; it < 640; it += NT_) {
            int ck = it & 15;
            int row = it >> 4;           // zi*8 + yi
            int yi = row & 7, zi = row >> 3;
            int gy = y0 + yi - 2, gz = z0 + zi - 2;
            if ((unsigned)gy < 32u && (unsigned)gz < 32u)
                CPA4(smb + SX_OFF + (uint32_t)(row * 36 + 2 + ck * 2) * 2,
                     xc + ((gz * 32 + gy) * 32 + ck * 2));
        }
    };
    auto stage_B = [&](int n, int nb) {
        const char* src = (const char*)g_wprep + (size_t)n * B_TILE;
        uint32_t dst = smb + SB_OFF + nb * B_TILE;
        for (int i = tid; i < B_TILE / 16; i += NT_)
            CPA16(dst + i * 16, src + i * 16);
    };
    auto build_A = [&](int nb) {
        char* Abase = (char*)smem + SA_OFF + nb * A_TILE;
        const int lin = byy * 36 + lid;
        const int m   = byy * 32 + lid;
        const uint32_t mx = (uint32_t)(m & 7) << 4;
#pragma unroll
        for (int j = 0; j < 16; ++j) {
            int k0 = bkq * 32 + 2 * j;
            uint32_t t0 = *(const unsigned short*)((const char*)xs +
                              (uint32_t)(tapoff[k0]     + lin) * 2);
            uint32_t t1 = *(const unsigned short*)((const char*)xs +
                              (uint32_t)(tapoff[k0 + 1] + lin) * 2);
            uint32_t hp = t0 | (t1 << 16);
            int khalf = k0 >> 6, c6 = k0 & 63;
            *(uint32_t*)(Abase + khalf * A_HALF +
                         (((uint32_t)(m * 128 + c6 * 2)) ^ mx)) = hp;
        }
    };

    // lane-invariant ldmatrix offsets
    const uint32_t aLane  = (uint32_t)((lid & 15) * 128 + ((lid & 16) ? 16 : 0));
    const uint32_t bLane4 = (uint32_t)((((lid & 7) + ((lid & 16) ? 8 : 0)) * 128) +
                                       ((lid & 8) ? 16 : 0));

    float acc[2][6][4];
#pragma unroll
    for (int mi = 0; mi < 2; ++mi)
#pragma unroll
        for (int ni = 0; ni < 6; ++ni)
#pragma unroll
            for (int r = 0; r < 4; ++r) acc[mi][ni][r] = 0.f;

    // ---- prologue ----
    stage_B(0, 0);
    stage_x(0);
    CPC(); CPW0();
    __syncthreads();
    build_A(0);
    __syncthreads();

    for (int c = 0; c < NCHUNK_; ++c) {
        const int bsel = c & 1;
        if (c + 1 < NCHUNK_) {
            stage_B(c + 1, bsel ^ 1);
            stage_x(c + 1);
            CPC();
        }

        const uint32_t AB = smb + SA_OFF + bsel * A_TILE;
        const uint32_t BB = smb + SB_OFF + bsel * B_TILE;

#pragma unroll
        for (int ks = 0; ks < 8; ++ks) {
            const uint32_t Ah = AB + (ks >> 2) * A_HALF;
            const uint32_t Bh = BB + (ks >> 2) * B_HALF;
            const uint32_t kso = (uint32_t)(ks & 3) * 32;
            uint32_t a0[4], a1[4];
            LDM4(a0, Ah + swz((uint32_t)(m0       * 128) + kso + aLane));
            LDM4(a1, Ah + swz((uint32_t)((m0+16)  * 128) + kso + aLane));
#pragma unroll
            for (int g = 0; g < 3; ++g) {
                if (g * 2 >= NG) break;
                uint32_t bh[4];
                LDM4(bh, Bh + swz((uint32_t)((n0 + g * 16) * 128) + kso + bLane4));
                MMAF16(acc[0][g * 2],     a0, bh[0], bh[1]);
                MMAF16(acc[1][g * 2],     a1, bh[0], bh[1]);
                MMAF16(acc[0][g * 2 + 1], a0, bh[2], bh[3]);
                MMAF16(acc[1][g * 2 + 1], a1, bh[2], bh[3]);
            }
        }

        if (c + 1 < NCHUNK_) {
            CPW0();
            __syncthreads();
            build_A(bsel ^ 1);
        }
        __syncthreads();
    }

    // ---- epilogue: accums -> smem, sigmoid gates, gated write to g_z ----
    float* sD = (float*)smem;   // [176][132] floats = 92928B, reuses tile smem
#pragma unroll
    for (int mi = 0; mi < 2; ++mi)
#pragma unroll
        for (int ni = 0; ni < 6; ++ni) {
            if (ni >= NG) break;
#pragma unroll
            for (int r = 0; r < 4; ++r) {
                int m  = m0 + mi * 16 + (lid >> 2) + ((r & 2) ? 8 : 0);
                int cc = n0 + ni * 8 + (lid & 3) * 2 + (r & 1);
                sD[cc * 132 + m] = acc[mi][ni][r];
            }
        }
    __syncthreads();

    for (int i = tid; i < 32 * 128; i += NT_) {
        int gi = i >> 7, mm = i & 127;
        int ad = (144 + gi) * 132 + mm;
        sD[ad] = 1.f / (1.f + expf(-(sD[ad] + sG[gi])));
    }
    __syncthreads();

    float* zb = g_z + (size_t)b * NCH_ * NSP_ + (size_t)z0 * 1024 + y0 * 32;
    for (int i = tid; i < 144 * 128; i += NT_) {
        int cc = i >> 7, mm = i & 127;
        float v = sD[cc * 132 + mm];
        float o;
        if (cc < 16) o = fmaxf(v + sS[cc], 0.f);
        else {
            int gi = (cc < 64) ? (cc - 16) / 3 : 16 + (cc - 64) / 5;
            o = v * sD[(144 + gi) * 132 + mm];
        }
        zb[(size_t)cc * NSP_ + mm] = o;
    }
}

// ---------------------------------------------------------------------------
// Depthwise 5^3 gaussian, stride2, pad2 -> (16,16,16). grid (4, 144, 4).
// 4 output z-planes per block: sZ[11][35][36], single barrier, div-free load.
// ---------------------------------------------------------------------------
__global__ __launch_bounds__(256)
void lowpass_kernel(float* __restrict__ out)
{
    extern __shared__ float sZ[];      // [11][35][36]
    __shared__ float sWg[125];

    const int zt = blockIdx.x;         // 0..3 -> zo0 = 4*zt
    const int c  = blockIdx.y;
    const int b  = blockIdx.z;
    const int tid = threadIdx.x;
    const int wrp = tid >> 5;
    const int lidl = tid & 31;

    if (tid < 125) {
        int kw = tid % 5, t = tid / 5;
        int kh = t % 5,  kd = t / 5;
        double g[5], s = 0.0;
#pragma unroll
        for (int r = 0; r < 5; ++r) {
            double d = (double)(r - 2);
            g[r] = exp(-d * d / 1.5);   // 2*sigma^2 = 1.5
            s += g[r];
        }
        sWg[tid] = (float)(g[kd] * g[kh] * g[kw] / (s * s * s));
    }

    const int zo0 = 4 * zt;
    const int zi0 = 2 * zo0 - 2;       // first input plane
    const float* zc = g_z + (size_t)(b * NCH_ + c) * NSP_;

    // ---- load 11x35 rows x 35 elems, warp-strided rows, incremental (zi,yi)
    {
        int zi = 0, yi = wrp;          // wrp < 8 < 35
        for (int r = wrp; r < 385; r += 8) {
            int gz = zi0 + zi;
            int gy = yi - 2;
            bool rowok = ((unsigned)gz < 32u) & ((unsigned)gy < 32u);
            const float* rowp = zc + (gz * 32 + gy) * 32;
            float* srow = sZ + (zi * 35 + yi) * 36;
            float v = 0.f;
            int gx = lidl - 2;
            if (rowok & ((unsigned)gx < 32u)) v = rowp[gx];
            srow[lidl] = v;
            if (lidl < 3) {
                float v2 = 0.f;
                int gx2 = lidl + 30;
                if (rowok & ((unsigned)gx2 < 32u)) v2 = rowp[gx2];
                srow[32 + lidl] = v2;
            }
            yi += 8; if (yi >= 35) { yi -= 35; zi += 1; }
        }
    }
    __syncthreads();

    // ---- compute: thread (xo,yo), 4 z-planes; kd-weights in registers
    const int xo = tid & 15;
    const int yo = tid >> 4;
    const float* bp = sZ + (2 * yo) * 36 + 2 * xo;

    float a0 = 0.f, a1 = 0.f, a2 = 0.f, a3 = 0.f;
#pragma unroll
    for (int kh = 0; kh < 5; ++kh) {
#pragma unroll
        for (int kw = 0; kw < 5; ++kw) {
            float w0 = sWg[(0 * 5 + kh) * 5 + kw];
            float w1 = sWg[(1 * 5 + kh) * 5 + kw];
            float w2 = sWg[(2 * 5 + kh) * 5 + kw];
            float w3 = sWg[(3 * 5 + kh) * 5 + kw];
            float w4 = sWg[(4 * 5 + kh) * 5 + kw];
            const int eo = kh * 36 + kw;
#pragma unroll
            for (int p = 0; p < 11; ++p) {
                float v = bp[p * 1260 + eo];
                // dz contributions: kd = p - 2*dz in [0,5)
                if (p - 0 >= 0 && p - 0 < 5) {
                    float w = (p == 0) ? w0 : (p == 1) ? w1 : (p == 2) ? w2
                            : (p == 3) ? w3 : w4;
                    a0 += w * v;
                }
                if (p - 2 >= 0 && p - 2 < 5) {
                    int kd = p - 2;
                    float w = (kd == 0) ? w0 : (kd == 1) ? w1 : (kd == 2) ? w2
                            : (kd == 3) ? w3 : w4;
                    a1 += w * v;
                }
                if (p - 4 >= 0 && p - 4 < 5) {
                    int kd = p - 4;
                    float w = (kd == 0) ? w0 : (kd == 1) ? w1 : (kd == 2) ? w2
                            : (kd == 3) ? w3 : w4;
                    a2 += w * v;
                }
                if (p - 6 >= 0 && p - 6 < 5) {
                    int kd = p - 6;
                    float w = (kd == 0) ? w0 : (kd == 1) ? w1 : (kd == 2) ? w2
                            : (kd == 3) ? w3 : w4;
                    a3 += w * v;
                }
            }
        }
    }

    float* ob = out + ((size_t)(b * NCH_ + c) * 16 + zo0) * 256 + yo * 16 + xo;
    ob[0]   = a0;
    ob[256] = a1;
    ob[512] = a2;
    ob[768] = a3;
}

// ---------------------------------------------------------------------------
extern "C" void kernel_launch(void* const* d_in, const int* in_sizes, int n_in,
                              void* d_out, int out_size)
{
    const float* x  = (const float*)d_in[0];   // (4,72,32,32,32)
    const float* W  = (const float*)d_in[1];   // (176,72,5,5,5)
    const float* sb = (const float*)d_in[2];   // (16,)
    const float* gb = (const float*)d_in[3];   // (32,)
    float* out = (float*)d_out;                // (4,144,16,16,16)

    cudaFuncSetAttribute(conv_mma_kernel,
                         cudaFuncAttributeMaxDynamicSharedMemorySize, SMEM_TOTAL);
    cudaFuncSetAttribute(lowpass_kernel,
                         cudaFuncAttributeMaxDynamicSharedMemorySize, LP_SMEM);

    prep_kernel<<<6336, 256>>>(W);
    prep_x_kernel<<<36864, 256>>>(x);
    conv_mma_kernel<<<dim3(8, 32, B_), NT_, SMEM_TOTAL>>>(sb, gb);
    lowpass_kernel<<<dim3(4, NCH_, B_), 256, LP_SMEM>>>(out);
}

// round 14
// speedup vs baseline: 1.0998x; 1.0238x over previous
#include <cuda_runtime.h>
#include <cuda_fp16.h>
#include <math.h>
#include <stdint.h>

// ---------------------------------------------------------------------------
// GatedBlock via mma.sync fp16 implicit GEMM (single-term):
//   D = x_f16 * w_f16 ;  conv3d(72->176,k5,pad2) => D[M=128, N=176], K=72*128
//   gate fused into the GEMM epilogue, then depthwise gaussian stride-2.
// Round 14: 2 CTAs/SM (256 thr, KC=64, smem 97KB) so an independent CTA
//   fills the other's barrier/staging bubbles. Lowpass = round-13 version.
// ---------------------------------------------------------------------------

#define B_      4
#define CI_     72
#define CO_     176
#define NSP_    (32*32*32)
#define NCH_    144

#define KC_     64
#define NCHUNK_ 144           // 72*128 / 64
#define A_TILE  16384         // 128 rows x 64 fp16
#define B_TILE  22528         // 176 rows x 64 fp16
#define NT_     256

__device__ float  g_z[(size_t)B_ * NCH_ * NSP_];
__device__ __half g_wprep[(size_t)NCHUNK_ * CO_ * KC_];  // fp16, pre-swizzled
__device__ __half g_xh[(size_t)B_ * CI_ * NSP_];         // fp16 x image

// ---- smem byte offsets (dynamic smem, conv kernel) ----
// [0, 92928) reused by epilogue sD[176][132]; persistent data above it.
#define SA_OFF    0                        // A: 2 x 16384 = 32768
#define SB_OFF    32768                    // B: 2 x 22528 -> 77824
#define SX_OFF    92928                    // xs: 1584 halves -> 96096
#define XS_VALS   1584
#define ST_OFF    96128                    // tapoff: 128 ints -> 96640
#define SSB_OFF   96640
#define SGB_OFF   96704
#define SMEM_TOTAL 96832

// ---- lowpass: dynamic smem sZ[11][35][36] floats ----
#define LP_SMEM   (11*35*36*4)             // 55440 B

// ---------------- helpers ----------------
__device__ __forceinline__ uint32_t smem_u32(const void* p){
    uint32_t a;
    asm("{ .reg .u64 t; cvta.to.shared.u64 t, %1; cvt.u32.u64 %0, t; }"
        : "=r"(a) : "l"(p));
    return a;
}
__device__ __forceinline__ uint32_t swz(uint32_t o){
    return o ^ (((o >> 7) & 7u) << 4);
}

#define CPA16(d,s) asm volatile("cp.async.cg.shared.global [%0], [%1], 16;" :: "r"(d), "l"(s))
#define CPA4(d,s)  asm volatile("cp.async.ca.shared.global [%0], [%1], 4;"  :: "r"(d), "l"(s))
#define CPC()      asm volatile("cp.async.commit_group;")
#define CPW0()     asm volatile("cp.async.wait_group 0;")

#define LDM4(r, a) \
    asm volatile("ldmatrix.sync.aligned.m8n8.x4.shared.b16 {%0,%1,%2,%3}, [%4];" \
        : "=r"((r)[0]),"=r"((r)[1]),"=r"((r)[2]),"=r"((r)[3]) : "r"(a))
#define LDM2(r, a) \
    asm volatile("ldmatrix.sync.aligned.m8n8.x2.shared.b16 {%0,%1}, [%2];" \
        : "=r"((r)[0]),"=r"((r)[1]) : "r"(a))

#define MMAF16(d, a, b0v, b1v) \
    asm volatile("mma.sync.aligned.m16n8k16.row.col.f32.f16.f16.f32 " \
        "{%0,%1,%2,%3}, {%4,%5,%6,%7}, {%8,%9}, {%0,%1,%2,%3};" \
        : "+f"((d)[0]),"+f"((d)[1]),"+f"((d)[2]),"+f"((d)[3]) \
        : "r"((a)[0]),"r"((a)[1]),"r"((a)[2]),"r"((a)[3]), "r"(b0v), "r"(b1v))

// ---------------------------------------------------------------------------
// Weight prep: reorder to K=(ci*128+tap), fp16, pre-apply the XOR swizzle.
// ---------------------------------------------------------------------------
__global__ void prep_kernel(const float* __restrict__ W)
{
    int e = blockIdx.x * 256 + threadIdx.x;   // 144*176*64 = 1,622,016 exact
    int col   = e & 63;
    int row   = (e >> 6) % CO_;
    int chunk = e / (CO_ * KC_);
    int k  = chunk * KC_ + col;
    int ci = k >> 7;
    int tap = k & 127;
    float v = (tap < 125) ? W[((size_t)row * CI_ + ci) * 125 + tap] : 0.f;
    uint32_t off = (uint32_t)(row * 128 + col * 2);
    uint32_t sw  = off ^ ((uint32_t)(row & 7) << 4);
    g_wprep[(size_t)chunk * (CO_ * KC_) + (sw >> 1)] = __float2half_rn(v);
}

__global__ void prep_x_kernel(const float* __restrict__ x)
{
    size_t i = (size_t)blockIdx.x * 256 + threadIdx.x;   // 9,437,184 exact
    g_xh[i] = __float2half_rn(x[i]);
}

// ---------------------------------------------------------------------------
// Main kernel: implicit GEMM + fused gate epilogue.
// grid (8 y-tiles, 32 z, 4 b), 256 threads, 2 CTAs/SM.
// warps: 4M x 2N, warp tile M=32, N=88.
// ---------------------------------------------------------------------------
__global__ __launch_bounds__(NT_, 2)
void conv_mma_kernel(const float* __restrict__ sbg, const float* __restrict__ gbg)
{
    extern __shared__ unsigned char smem[];
    const uint32_t smb = smem_u32(smem);

    const int tid = threadIdx.x;
    const int wid = tid >> 5;
    const int lid = tid & 31;
    const int b  = blockIdx.z;
    const int z0 = blockIdx.y;
    const int y0 = blockIdx.x * 4;

    // builder role: 8 warps = 4 y-groups x 2 k-halves (32 k each)
    const int byy = wid & 3, bkh = wid >> 2;
    // mma role: 4 M-groups x 2 N-halves
    const int m0 = (wid >> 1) * 32;
    const int n0 = (wid & 1) * 88;

    __half* xs    = (__half*)(smem + SX_OFF);
    int*   tapoff = (int*)(smem + ST_OFF);
    float* sS     = (float*)(smem + SSB_OFF);
    float* sG     = (float*)(smem + SGB_OFF);

    for (int i = tid; i < XS_VALS; i += NT_) xs[i] = __ushort_as_half(0);
    if (tid < 128) {
        int tap = tid;
        int kd = tap / 25, r = tap % 25;
        int kh = r / 5, kw = r % 5;
        tapoff[tid] = (tap < 125) ? (kd * 8 + kh) * 36 + kw : 1440;
    }
    if (tid < 16) sS[tid] = sbg[tid];
    if (tid < 32) sG[tid] = gbg[tid];
    __syncthreads();

    const __half* xb = g_xh + (size_t)b * CI_ * NSP_;

    auto stage_x = [&](int ci) {
        const __half* xc = xb + (size_t)ci * NSP_;
        for (int it = tid; it < 640; it += NT_) {
            int ck = it & 15;
            int row = it >> 4;           // zi*8 + yi
            int yi = row & 7, zi = row >> 3;
            int gy = y0 + yi - 2, gz = z0 + zi - 2;
            if ((unsigned)gy < 32u && (unsigned)gz < 32u)
                CPA4(smb + SX_OFF + (uint32_t)(row * 36 + 2 + ck * 2) * 2,
                     xc + ((gz * 32 + gy) * 32 + ck * 2));
        }
    };
    auto stage_B = [&](int n, int nb) {
        const char* src = (const char*)g_wprep + (size_t)n * B_TILE;
        uint32_t dst = smb + SB_OFF + nb * B_TILE;
        for (int i = tid; i < B_TILE / 16; i += NT_)
            CPA16(dst + i * 16, src + i * 16);
    };
    auto build_A = [&](int n, int nb) {
        char* Abase = (char*)smem + SA_OFF + nb * A_TILE;
        const int tb  = (n & 1) * 64;
        const int lin = byy * 36 + lid;
        const int m   = byy * 32 + lid;
        const uint32_t mx = (uint32_t)(m & 7) << 4;
#pragma unroll
        for (int j = 0; j < 16; ++j) {
            int k0 = bkh * 32 + 2 * j;
            uint32_t t0 = *(const unsigned short*)((const char*)xs +
                              (uint32_t)(tapoff[tb + k0]     + lin) * 2);
            uint32_t t1 = *(const unsigned short*)((const char*)xs +
                              (uint32_t)(tapoff[tb + k0 + 1] + lin) * 2);
            uint32_t hp = t0 | (t1 << 16);
            *(uint32_t*)(Abase + (((uint32_t)(m * 128 + k0 * 2)) ^ mx)) = hp;
        }
    };

    // lane-invariant ldmatrix offsets
    const uint32_t aLane  = (uint32_t)((lid & 15) * 128 + ((lid & 16) ? 16 : 0));
    const uint32_t bLane4 = (uint32_t)((((lid & 7) + ((lid & 16) ? 8 : 0)) * 128) +
                                       ((lid & 8) ? 16 : 0));
    const uint32_t bLane2 = (uint32_t)((lid & 7) * 128 + ((lid & 8) ? 16 : 0));

    float acc[2][11][4];
#pragma unroll
    for (int mi = 0; mi < 2; ++mi)
#pragma unroll
        for (int ni = 0; ni < 11; ++ni)
#pragma unroll
            for (int r = 0; r < 4; ++r) acc[mi][ni][r] = 0.f;

    // ---- prologue ----
    stage_B(0, 0);
    stage_x(0);
    CPC(); CPW0();
    __syncthreads();
    build_A(0, 0);
    __syncthreads();

    for (int c = 0; c < NCHUNK_; ++c) {
        const int bsel = c & 1;
        if (c + 1 < NCHUNK_) {
            stage_B(c + 1, bsel ^ 1);
            if (((c + 1) & 1) == 0) stage_x((c + 1) >> 1);
            CPC();
        }

        const uint32_t AhB = smb + SA_OFF + bsel * A_TILE;
        const uint32_t BhB = smb + SB_OFF + bsel * B_TILE;

#pragma unroll
        for (int ks = 0; ks < 4; ++ks) {
            const uint32_t kso = (uint32_t)ks * 32;
            uint32_t a0[4], a1[4];
            LDM4(a0, AhB + swz((uint32_t)(m0      * 128) + kso + aLane));
            LDM4(a1, AhB + swz((uint32_t)((m0+16) * 128) + kso + aLane));
#pragma unroll
            for (int nip = 0; nip < 5; ++nip) {
                uint32_t bh[4];
                LDM4(bh, BhB + swz((uint32_t)((n0 + nip * 16) * 128) + kso + bLane4));
                MMAF16(acc[0][nip * 2],     a0, bh[0], bh[1]);
                MMAF16(acc[1][nip * 2],     a1, bh[0], bh[1]);
                MMAF16(acc[0][nip * 2 + 1], a0, bh[2], bh[3]);
                MMAF16(acc[1][nip * 2 + 1], a1, bh[2], bh[3]);
            }
            {   // n-group 10 (cols 80..87)
                uint32_t b2[2];
                LDM2(b2, BhB + swz((uint32_t)((n0 + 80) * 128) + kso + bLane2));
                MMAF16(acc[0][10], a0, b2[0], b2[1]);
                MMAF16(acc[1][10], a1, b2[0], b2[1]);
            }
        }

        if (c + 1 < NCHUNK_) {
            CPW0();
            __syncthreads();
            build_A(c + 1, bsel ^ 1);
        }
        __syncthreads();
    }

    // ---- epilogue: accums -> smem, sigmoid gates, gated write to g_z ----
    float* sD = (float*)smem;   // [176][132] floats = 92928B, reuses tile smem
#pragma unroll
    for (int mi = 0; mi < 2; ++mi)
#pragma unroll
        for (int ni = 0; ni < 11; ++ni)
#pragma unroll
            for (int r = 0; r < 4; ++r) {
                int m  = m0 + mi * 16 + (lid >> 2) + ((r & 2) ? 8 : 0);
                int cc = n0 + ni * 8 + (lid & 3) * 2 + (r & 1);
                sD[cc * 132 + m] = acc[mi][ni][r];
            }
    __syncthreads();

    for (int i = tid; i < 32 * 128; i += NT_) {
        int gi = i >> 7, mm = i & 127;
        int ad = (144 + gi) * 132 + mm;
        sD[ad] = 1.f / (1.f + expf(-(sD[ad] + sG[gi])));
    }
    __syncthreads();

    float* zb = g_z + (size_t)b * NCH_ * NSP_ + (size_t)z0 * 1024 + y0 * 32;
    for (int i = tid; i < 144 * 128; i += NT_) {
        int cc = i >> 7, mm = i & 127;
        float v = sD[cc * 132 + mm];
        float o;
        if (cc < 16) o = fmaxf(v + sS[cc], 0.f);
        else {
            int gi = (cc < 64) ? (cc - 16) / 3 : 16 + (cc - 64) / 5;
            o = v * sD[(144 + gi) * 132 + mm];
        }
        zb[(size_t)cc * NSP_ + mm] = o;
    }
}

// ---------------------------------------------------------------------------
// Depthwise 5^3 gaussian, stride2, pad2 -> (16,16,16). grid (4, 144, 4).
// 4 output z-planes per block: sZ[11][35][36], single barrier, div-free load.
// ---------------------------------------------------------------------------
__global__ __launch_bounds__(256)
void lowpass_kernel(float* __restrict__ out)
{
    extern __shared__ float sZ[];      // [11][35][36]
    __shared__ float sWg[125];

    const int zt = blockIdx.x;         // 0..3 -> zo0 = 4*zt
    const int c  = blockIdx.y;
    const int b  = blockIdx.z;
    const int tid = threadIdx.x;
    const int wrp = tid >> 5;
    const int lidl = tid & 31;

    if (tid < 125) {
        int kw = tid % 5, t = tid / 5;
        int kh = t % 5,  kd = t / 5;
        double g[5], s = 0.0;
#pragma unroll
        for (int r = 0; r < 5; ++r) {
            double d = (double)(r - 2);
            g[r] = exp(-d * d / 1.5);   // 2*sigma^2 = 1.5
            s += g[r];
        }
        sWg[tid] = (float)(g[kd] * g[kh] * g[kw] / (s * s * s));
    }

    const int zo0 = 4 * zt;
    const int zi0 = 2 * zo0 - 2;       // first input plane
    const float* zc = g_z + (size_t)(b * NCH_ + c) * NSP_;

    // load 11x35 rows x 35 elems, warp-strided rows, incremental (zi,yi)
    {
        int zi = 0, yi = wrp;          // wrp < 8 < 35
        for (int r = wrp; r < 385; r += 8) {
            int gz = zi0 + zi;
            int gy = yi - 2;
            bool rowok = ((unsigned)gz < 32u) & ((unsigned)gy < 32u);
            const float* rowp = zc + (gz * 32 + gy) * 32;
            float* srow = sZ + (zi * 35 + yi) * 36;
            float v = 0.f;
            int gx = lidl - 2;
            if (rowok & ((unsigned)gx < 32u)) v = rowp[gx];
            srow[lidl] = v;
            if (lidl < 3) {
                float v2 = 0.f;
                int gx2 = lidl + 30;
                if (rowok & ((unsigned)gx2 < 32u)) v2 = rowp[gx2];
                srow[32 + lidl] = v2;
            }
            yi += 8; if (yi >= 35) { yi -= 35; zi += 1; }
        }
    }
    __syncthreads();

    const int xo = tid & 15;
    const int yo = tid >> 4;
    const float* bp = sZ + (2 * yo) * 36 + 2 * xo;

    float a0 = 0.f, a1 = 0.f, a2 = 0.f, a3 = 0.f;
#pragma unroll
    for (int kh = 0; kh < 5; ++kh) {
#pragma unroll
        for (int kw = 0; kw < 5; ++kw) {
            float w0 = sWg[(0 * 5 + kh) * 5 + kw];
            float w1 = sWg[(1 * 5 + kh) * 5 + kw];
            float w2 = sWg[(2 * 5 + kh) * 5 + kw];
            float w3 = sWg[(3 * 5 + kh) * 5 + kw];
            float w4 = sWg[(4 * 5 + kh) * 5 + kw];
            const int eo = kh * 36 + kw;
#pragma unroll
            for (int p = 0; p < 11; ++p) {
                float v = bp[p * 1260 + eo];
                if (p - 0 >= 0 && p - 0 < 5) {
                    float w = (p == 0) ? w0 : (p == 1) ? w1 : (p == 2) ? w2
                            : (p == 3) ? w3 : w4;
                    a0 += w * v;
                }
                if (p - 2 >= 0 && p - 2 < 5) {
                    int kd = p - 2;
                    float w = (kd == 0) ? w0 : (kd == 1) ? w1 : (kd == 2) ? w2
                            : (kd == 3) ? w3 : w4;
                    a1 += w * v;
                }
                if (p - 4 >= 0 && p - 4 < 5) {
                    int kd = p - 4;
                    float w = (kd == 0) ? w0 : (kd == 1) ? w1 : (kd == 2) ? w2
                            : (kd == 3) ? w3 : w4;
                    a2 += w * v;
                }
                if (p - 6 >= 0 && p - 6 < 5) {
                    int kd = p - 6;
                    float w = (kd == 0) ? w0 : (kd == 1) ? w1 : (kd == 2) ? w2
                            : (kd == 3) ? w3 : w4;
                    a3 += w * v;
                }
            }
        }
    }

    float* ob = out + ((size_t)(b * NCH_ + c) * 16 + zo0) * 256 + yo * 16 + xo;
    ob[0]   = a0;
    ob[256] = a1;
    ob[512] = a2;
    ob[768] = a3;
}

// ---------------------------------------------------------------------------
extern "C" void kernel_launch(void* const* d_in, const int* in_sizes, int n_in,
                              void* d_out, int out_size)
{
    const float* x  = (const float*)d_in[0];   // (4,72,32,32,32)
    const float* W  = (const float*)d_in[1];   // (176,72,5,5,5)
    const float* sb = (const float*)d_in[2];   // (16,)
    const float* gb = (const float*)d_in[3];   // (32,)
    float* out = (float*)d_out;                // (4,144,16,16,16)

    cudaFuncSetAttribute(conv_mma_kernel,
                         cudaFuncAttributeMaxDynamicSharedMemorySize, SMEM_TOTAL);
    cudaFuncSetAttribute(lowpass_kernel,
                         cudaFuncAttributeMaxDynamicSharedMemorySize, LP_SMEM);

    prep_kernel<<<6336, 256>>>(W);
    prep_x_kernel<<<36864, 256>>>(x);
    conv_mma_kernel<<<dim3(8, 32, B_), NT_, SMEM_TOTAL>>>(sb, gb);
    lowpass_kernel<<<dim3(4, NCH_, B_), 256, LP_SMEM>>>(out);
}